// round 13
// baseline (speedup 1.0000x reference)
#include <cuda_runtime.h>
#include <cuda_bf16.h>
#include <cuda_fp16.h>
#include <cstdint>

#define NN 50000
#define EE 800000
#define F1 4096
#define F2 256
#define F3 128
#define SCAN_NB ((NN + 255) / 256)

// ---------------------------------------------------------------- scratch
__device__ int   g_is64;
__device__ int   g_deg[NN];
__device__ int   g_cnt[NN];
__device__ int   g_part[SCAN_NB];
__device__ int   g_rowoff[NN + 1];
__device__ int   g_csr[EE];
__device__ float g_g1[NN * F2];    // dinv-scaled layer-1 dense output
__device__ float g_h1[NN * F2];    // relu'd layer-1 output
__device__ float g_g2[NN * F3];    // dinv-scaled layer-2 dense output
__device__ uint16_t g_B1h[F1 * F2];   // W1 fp16
__device__ uint16_t g_B2h[F2 * F3];   // W2 fp16

// ---------------------------------------------------------------- helpers
__device__ __forceinline__ uint32_t smem_u32(const void* p) {
    uint32_t a;
    asm("{ .reg .u64 t; cvta.to.shared.u64 t, %1; cvt.u32.u64 %0, t; }"
        : "=r"(a) : "l"(p));
    return a;
}
__device__ __forceinline__ void ldsm_x4(uint32_t& r0, uint32_t& r1, uint32_t& r2,
                                        uint32_t& r3, uint32_t addr) {
    asm volatile("ldmatrix.sync.aligned.m8n8.x4.shared.b16 {%0,%1,%2,%3}, [%4];"
                 : "=r"(r0), "=r"(r1), "=r"(r2), "=r"(r3) : "r"(addr));
}
__device__ __forceinline__ void ldsm_x4_t(uint32_t& r0, uint32_t& r1, uint32_t& r2,
                                          uint32_t& r3, uint32_t addr) {
    asm volatile("ldmatrix.sync.aligned.m8n8.x4.trans.shared.b16 {%0,%1,%2,%3}, [%4];"
                 : "=r"(r0), "=r"(r1), "=r"(r2), "=r"(r3) : "r"(addr));
}
__device__ __forceinline__ void mma_f16(float* d, const uint32_t* a,
                                        const uint32_t* b) {
    asm volatile(
        "mma.sync.aligned.m16n8k16.row.col.f32.f16.f16.f32 "
        "{%0,%1,%2,%3}, {%4,%5,%6,%7}, {%8,%9}, {%0,%1,%2,%3};"
        : "+f"(d[0]), "+f"(d[1]), "+f"(d[2]), "+f"(d[3])
        : "r"(a[0]), "r"(a[1]), "r"(a[2]), "r"(a[3]), "r"(b[0]), "r"(b[1]));
}
__device__ __forceinline__ void cp_async16(uint32_t saddr, const void* gptr) {
    asm volatile("cp.async.cg.shared.global [%0], [%1], 16;"
                 :: "r"(saddr), "l"(gptr) : "memory");
}
__device__ __forceinline__ void cp_async_commit() {
    asm volatile("cp.async.commit_group;" ::: "memory");
}
__device__ __forceinline__ void cp_async_wait0() {
    asm volatile("cp.async.wait_group 0;" ::: "memory");
}
__device__ __forceinline__ void cp_async_wait1() {
    asm volatile("cp.async.wait_group 1;" ::: "memory");
}
__device__ __forceinline__ unsigned pack2h(float a, float b) {
    __half2 t = __floats2half2_rn(a, b);
    return *reinterpret_cast<unsigned*>(&t);
}

__device__ __forceinline__ int edge_idx(const void* ei, int which, int e) {
    if (g_is64) return (int)((const long long*)ei)[(size_t)which * EE + e];
    return ((const int*)ei)[(size_t)which * EE + e];
}

// ---------------------------------------------------------------- setup
__global__ void detect_init_kernel(const int* __restrict__ ei32) {
    int i = blockIdx.x * blockDim.x + threadIdx.x;
    if (i < NN) { g_deg[i] = 0; g_cnt[i] = 0; }
    if (i == 0) {
        int all_zero = 1;
        for (int j = 0; j < 128; j++)
            if (ei32[2 * j + 1] != 0) { all_zero = 0; break; }
        g_is64 = all_zero;
    }
}
__global__ void count_deg_kernel(const void* __restrict__ ei) {
    int e = blockIdx.x * blockDim.x + threadIdx.x;
    if (e < EE) {
        int d = edge_idx(ei, 1, e);
        if ((unsigned)d < (unsigned)NN) atomicAdd(&g_deg[d], 1);
    }
}

// -------- multi-block exclusive scan of g_deg -> g_rowoff
__global__ void __launch_bounds__(256) scan_partial_kernel() {
    __shared__ int s[256];
    int t = threadIdx.x;
    int idx = blockIdx.x * 256 + t;
    s[t] = (idx < NN) ? g_deg[idx] : 0;
    __syncthreads();
#pragma unroll
    for (int off = 128; off > 0; off >>= 1) {
        if (t < off) s[t] += s[t + off];
        __syncthreads();
    }
    if (t == 0) g_part[blockIdx.x] = s[0];
}
__global__ void __launch_bounds__(256) scan_part_scan_kernel() {
    __shared__ int s[256];
    int t = threadIdx.x;
    int v = (t < SCAN_NB) ? g_part[t] : 0;
    s[t] = v;
    __syncthreads();
#pragma unroll
    for (int off = 1; off < 256; off <<= 1) {
        int u = (t >= off) ? s[t - off] : 0;
        __syncthreads();
        s[t] += u;
        __syncthreads();
    }
    if (t < SCAN_NB) g_part[t] = s[t] - v;  // exclusive
}
__global__ void __launch_bounds__(256) rowoff_kernel() {
    __shared__ int s[256];
    int t = threadIdx.x;
    int idx = blockIdx.x * 256 + t;
    int v = (idx < NN) ? g_deg[idx] : 0;
    s[t] = v;
    __syncthreads();
#pragma unroll
    for (int off = 1; off < 256; off <<= 1) {
        int u = (t >= off) ? s[t - off] : 0;
        __syncthreads();
        s[t] += u;
        __syncthreads();
    }
    if (idx <= NN) g_rowoff[idx] = g_part[blockIdx.x] + (s[t] - v);
}

__global__ void fill_csr_kernel(const void* __restrict__ ei) {
    int e = blockIdx.x * blockDim.x + threadIdx.x;
    if (e >= EE) return;
    int s = edge_idx(ei, 0, e);
    int d = edge_idx(ei, 1, e);
    if ((unsigned)s >= (unsigned)NN || (unsigned)d >= (unsigned)NN) return;
    int pos = g_rowoff[d] + atomicAdd(&g_cnt[d], 1);
    g_csr[pos] = s;
}

// ---------------------------------------------------------------- W converts
__global__ void __launch_bounds__(256) split_W1_kernel(const float* __restrict__ W1) {
    int i = blockIdx.x * blockDim.x + threadIdx.x;
    if (i >= F1 * F2) return;
    __half h = __float2half_rn(W1[i]);
    g_B1h[i] = *reinterpret_cast<uint16_t*>(&h);
}
__global__ void __launch_bounds__(256) split_W2_kernel(const float* __restrict__ W2) {
    int i = blockIdx.x * blockDim.x + threadIdx.x;
    if (i >= F2 * F3) return;
    __half h = __float2half_rn(W2[i]);
    g_B2h[i] = *reinterpret_cast<uint16_t*>(&h);
}

// ---------------------------------------------------------------- GEMM (fp16 mma.sync, single product)
// C[m, n0+n] = rsqrt(deg[m]+1) * sum_k fp16(A[m,k]) * fp16(B[k, n0+n])
// CTA tile 128 x 128, 256 threads, 2 CTAs/SM, BK=32, 3-stage cp.async for B.
#define SA_STRIDE 80
#define GEMM_N 128
#define GEMM_SB (GEMM_N * 2 + 16)      // 272
#define GEMM_AH 0
#define GEMM_BH (128 * SA_STRIDE)      // 10240
#define GEMM_BUFB (GEMM_BH + 32 * GEMM_SB)   // 18944
#define GEMM_SMEM (3 * GEMM_BUFB)            // 56832

template <int K, int BW>
__device__ __forceinline__ void gemm_mma_dev(const float* __restrict__ A,
                                             const uint16_t* __restrict__ Bh,
                                             float* __restrict__ C) {
    constexpr int T = K / 32;

    extern __shared__ char smem[];
    const uint32_t sb = smem_u32(smem);
    const int tid = threadIdx.x;
    const int lane = tid & 31;
    const int wid = tid >> 5;           // 0..7
    const int wm = wid >> 1;            // 0..3  (rows wm*32)
    const int wn = wid & 1;             // 0..1  (cols wn*64)
    const int m0 = blockIdx.y * 128;
    const int n0 = blockIdx.x * GEMM_N;

    float acc[2][8][4];
#pragma unroll
    for (int a = 0; a < 2; a++)
#pragma unroll
        for (int b = 0; b < 8; b++)
#pragma unroll
            for (int c = 0; c < 4; c++) acc[a][b][c] = 0.f;

    float4 pa[4];
    const int ar = tid >> 3, ac = tid & 7;

    auto load_A = [&](int t) {
        const float* xa = A + (size_t)m0 * K + t * 32;
#pragma unroll
        for (int j = 0; j < 4; j++) {
            int row = ar + j * 32;
            pa[j] = (m0 + row < NN)
                        ? *reinterpret_cast<const float4*>(xa + (size_t)row * K + ac * 4)
                        : make_float4(0.f, 0.f, 0.f, 0.f);
        }
    };

    auto issue_B = [&](int t, int buf) {
        const uint16_t* bh = Bh + (size_t)(t * 32) * BW + n0;
        const uint32_t base = sb + buf * GEMM_BUFB;
#pragma unroll
        for (int i = 0; i < 2; i++) {
            int idx = tid + i * 256;
            int k = idx >> 4, c = idx & 15;
            cp_async16(base + GEMM_BH + k * GEMM_SB + c * 16, bh + (size_t)k * BW + c * 8);
        }
        cp_async_commit();
    };

    auto store_A = [&](int buf) {
        char* sbuf = smem + buf * GEMM_BUFB;
#pragma unroll
        for (int j = 0; j < 4; j++) {
            int r = ar + j * 32;
            float4 v = pa[j];
            uint2 hi = make_uint2(pack2h(v.x, v.y), pack2h(v.z, v.w));
            *reinterpret_cast<uint2*>(sbuf + GEMM_AH + r * SA_STRIDE + ac * 8) = hi;
        }
    };

    auto compute = [&](int buf) {
        const uint32_t bufb = sb + buf * GEMM_BUFB;
#pragma unroll
        for (int ks = 0; ks < 2; ks++) {
            uint32_t Ah[2][4];
#pragma unroll
            for (int mi = 0; mi < 2; mi++) {
                uint32_t addr = bufb + GEMM_AH +
                                (wm * 32 + mi * 16 + (lane & 15)) * SA_STRIDE +
                                (ks * 16 + (lane >> 4) * 8) * 2;
                ldsm_x4(Ah[mi][0], Ah[mi][1], Ah[mi][2], Ah[mi][3], addr);
            }
#pragma unroll
            for (int np = 0; np < 4; np++) {
                uint32_t baddr = bufb + GEMM_BH + (ks * 16 + (lane & 15)) * GEMM_SB +
                                 (wn * 64 + np * 16 + (lane >> 4) * 8) * 2;
                uint32_t bh[4];
                ldsm_x4_t(bh[0], bh[1], bh[2], bh[3], baddr);
                mma_f16(acc[0][np * 2 + 0], Ah[0], bh + 0);
                mma_f16(acc[1][np * 2 + 0], Ah[1], bh + 0);
                mma_f16(acc[0][np * 2 + 1], Ah[0], bh + 2);
                mma_f16(acc[1][np * 2 + 1], Ah[1], bh + 2);
            }
        }
    };

    // prologue: stage 0 fully, B(1) in flight, A(1) in regs
    load_A(0);
    issue_B(0, 0);
    store_A(0);
    load_A(1);
    issue_B(1, 1);
    cp_async_wait1();
    __syncthreads();

    int b0 = 0, b1 = 1, b2 = 2;
    for (int t = 0; t < T; t++) {
        if (t + 1 < T) store_A(b1);
        if (t + 2 < T) { load_A(t + 2); issue_B(t + 2, b2); }
        compute(b0);
        if (t + 1 < T) {
            if (t + 2 < T) cp_async_wait1(); else cp_async_wait0();
            __syncthreads();
        }
        int tmp = b0; b0 = b1; b1 = b2; b2 = tmp;
    }

    // epilogue: scale by rsqrt(deg+1), write C
#pragma unroll
    for (int mi = 0; mi < 2; mi++) {
        int r0 = m0 + wm * 32 + mi * 16 + (lane >> 2);
        int r1 = r0 + 8;
        float s0 = (r0 < NN) ? rsqrtf((float)g_deg[r0] + 1.0f) : 0.f;
        float s1 = (r1 < NN) ? rsqrtf((float)g_deg[r1] + 1.0f) : 0.f;
#pragma unroll
        for (int nt = 0; nt < 8; nt++) {
            int col = n0 + wn * 64 + nt * 8 + (lane & 3) * 2;
            if (r0 < NN) {
                float2 v = make_float2(acc[mi][nt][0] * s0, acc[mi][nt][1] * s0);
                *reinterpret_cast<float2*>(C + (size_t)r0 * BW + col) = v;
            }
            if (r1 < NN) {
                float2 v = make_float2(acc[mi][nt][2] * s1, acc[mi][nt][3] * s1);
                *reinterpret_cast<float2*>(C + (size_t)r1 * BW + col) = v;
            }
        }
    }
}

__global__ void __launch_bounds__(256, 2) gemm1_kernel(const float* __restrict__ x) {
    gemm_mma_dev<F1, F2>(x, g_B1h, g_g1);
}
__global__ void __launch_bounds__(256, 2) gemm2_kernel() {
    gemm_mma_dev<F2, F3>(g_h1, g_B2h, g_g2);
}

// ---------------------------------------------------------------- aggregation
// out[d,c] = post( rsqrt(deg[d]+1) * (g[d,c] + sum_{s in CSR[d]} g[s,c]) + bias[c] )
// One node per (F/4)-thread group; float4 per thread; CSR index is a uniform
// broadcast load; edge loop unrolled x2 with dual accumulators (MLP=2).
template <int F, bool RELU>
__device__ __forceinline__ void agg_dev(const float* __restrict__ g,
                                        const float* __restrict__ bias,
                                        float* __restrict__ out) {
    constexpr int TPN = F / 4;               // threads per node
    constexpr int NPB = 256 / TPN;           // nodes per block
    int node = blockIdx.x * NPB + threadIdx.x / TPN;
    if (node >= NN) return;
    int c4 = (threadIdx.x % TPN) * 4;

    int start = g_rowoff[node];
    int end = g_rowoff[node + 1];

    float4 acc = *reinterpret_cast<const float4*>(g + (size_t)node * F + c4);  // self
    float4 acc2 = make_float4(0.f, 0.f, 0.f, 0.f);

    int i = start;
    for (; i + 1 < end; i += 2) {
        int s0 = g_csr[i];
        int s1 = g_csr[i + 1];
        float4 v0 = *reinterpret_cast<const float4*>(g + (size_t)s0 * F + c4);
        float4 v1 = *reinterpret_cast<const float4*>(g + (size_t)s1 * F + c4);
        acc.x += v0.x; acc.y += v0.y; acc.z += v0.z; acc.w += v0.w;
        acc2.x += v1.x; acc2.y += v1.y; acc2.z += v1.z; acc2.w += v1.w;
    }
    if (i < end) {
        int s0 = g_csr[i];
        float4 v0 = *reinterpret_cast<const float4*>(g + (size_t)s0 * F + c4);
        acc.x += v0.x; acc.y += v0.y; acc.z += v0.z; acc.w += v0.w;
    }
    acc.x += acc2.x; acc.y += acc2.y; acc.z += acc2.z; acc.w += acc2.w;

    float s = rsqrtf((float)g_deg[node] + 1.0f);
    float4 bb = *reinterpret_cast<const float4*>(bias + c4);
    float4 r;
    r.x = fmaf(acc.x, s, bb.x);
    r.y = fmaf(acc.y, s, bb.y);
    r.z = fmaf(acc.z, s, bb.z);
    r.w = fmaf(acc.w, s, bb.w);
    if (RELU) {
        r.x = fmaxf(r.x, 0.f);
        r.y = fmaxf(r.y, 0.f);
        r.z = fmaxf(r.z, 0.f);
        r.w = fmaxf(r.w, 0.f);
    }
    *reinterpret_cast<float4*>(out + (size_t)node * F + c4) = r;
}

__global__ void __launch_bounds__(256) agg1_kernel(const float* __restrict__ b1) {
    agg_dev<F2, true>(g_g1, b1, g_h1);
}
__global__ void __launch_bounds__(256) agg2_kernel(const float* __restrict__ b2,
                                                   float* __restrict__ out) {
    agg_dev<F3, false>(g_g2, b2, out);
}

// ---------------------------------------------------------------- launch
extern "C" void kernel_launch(void* const* d_in, const int* in_sizes, int n_in,
                              void* d_out, int out_size) {
    const float* x = (const float*)d_in[0];
    const void* ei = d_in[1];
    const float* W1 = (const float*)d_in[2];
    const float* b1 = (const float*)d_in[3];
    const float* W2 = (const float*)d_in[4];
    const float* b2 = (const float*)d_in[5];
    float* out = (float*)d_out;

    cudaFuncSetAttribute(gemm1_kernel,
                         cudaFuncAttributeMaxDynamicSharedMemorySize, GEMM_SMEM);
    cudaFuncSetAttribute(gemm2_kernel,
                         cudaFuncAttributeMaxDynamicSharedMemorySize, GEMM_SMEM);

    // Launch order chosen so gemm1 is the 4th launch (ncu capture slot).
    split_W1_kernel<<<(F1 * F2 + 255) / 256, 256>>>(W1);            // 1
    detect_init_kernel<<<(NN + 255) / 256, 256>>>((const int*)ei);  // 2
    count_deg_kernel<<<(EE + 255) / 256, 256>>>(ei);                // 3
    {
        dim3 grid(F2 / GEMM_N, (NN + 127) / 128);                   // (2, 391)
        gemm1_kernel<<<grid, 256, GEMM_SMEM>>>(x);                  // 4
    }

    // CSR build (independent of gemm1)
    scan_partial_kernel<<<SCAN_NB, 256>>>();
    scan_part_scan_kernel<<<1, 256>>>();
    rowoff_kernel<<<SCAN_NB, 256>>>();
    fill_csr_kernel<<<(EE + 255) / 256, 256>>>(ei);

    {
        constexpr int NPB1 = 256 / (F2 / 4);   // 4 nodes per block
        agg1_kernel<<<(NN + NPB1 - 1) / NPB1, 256>>>(b1);
    }

    split_W2_kernel<<<(F2 * F3 + 255) / 256, 256>>>(W2);
    {
        dim3 grid(F3 / GEMM_N, (NN + 127) / 128);                   // (1, 391)
        gemm2_kernel<<<grid, 256, GEMM_SMEM>>>();
    }
    {
        constexpr int NPB2 = 256 / (F3 / 4);   // 8 nodes per block
        agg2_kernel<<<(NN + NPB2 - 1) / NPB2, 256>>>(b2, out);
    }
}

// round 14
// speedup vs baseline: 1.1845x; 1.1845x over previous
#include <cuda_runtime.h>
#include <cuda_bf16.h>
#include <cuda_fp16.h>
#include <cstdint>

#define NN 50000
#define EE 800000
#define F1 4096
#define F2 256
#define F3 128
#define SCAN_NB ((NN + 255) / 256)

// ---------------------------------------------------------------- scratch
__device__ int   g_is64;
__device__ int   g_deg[NN];
__device__ int   g_cnt[NN];
__device__ int   g_part[SCAN_NB];
__device__ int   g_rowoff[NN + 1];
__device__ int   g_csr[EE];
__device__ float g_g1[NN * F2];    // dinv-scaled layer-1 dense output
__device__ float g_h1[NN * F2];    // relu'd layer-1 output
__device__ float g_g2[NN * F3];    // dinv-scaled layer-2 dense output
__device__ uint16_t g_B1h[F1 * F2];   // W1 fp16
__device__ uint16_t g_B2h[F2 * F3];   // W2 fp16

// ---------------------------------------------------------------- helpers
__device__ __forceinline__ uint32_t smem_u32(const void* p) {
    uint32_t a;
    asm("{ .reg .u64 t; cvta.to.shared.u64 t, %1; cvt.u32.u64 %0, t; }"
        : "=r"(a) : "l"(p));
    return a;
}
__device__ __forceinline__ void ldsm_x4(uint32_t& r0, uint32_t& r1, uint32_t& r2,
                                        uint32_t& r3, uint32_t addr) {
    asm volatile("ldmatrix.sync.aligned.m8n8.x4.shared.b16 {%0,%1,%2,%3}, [%4];"
                 : "=r"(r0), "=r"(r1), "=r"(r2), "=r"(r3) : "r"(addr));
}
__device__ __forceinline__ void ldsm_x4_t(uint32_t& r0, uint32_t& r1, uint32_t& r2,
                                          uint32_t& r3, uint32_t addr) {
    asm volatile("ldmatrix.sync.aligned.m8n8.x4.trans.shared.b16 {%0,%1,%2,%3}, [%4];"
                 : "=r"(r0), "=r"(r1), "=r"(r2), "=r"(r3) : "r"(addr));
}
__device__ __forceinline__ void mma_f16(float* d, const uint32_t* a,
                                        const uint32_t* b) {
    asm volatile(
        "mma.sync.aligned.m16n8k16.row.col.f32.f16.f16.f32 "
        "{%0,%1,%2,%3}, {%4,%5,%6,%7}, {%8,%9}, {%0,%1,%2,%3};"
        : "+f"(d[0]), "+f"(d[1]), "+f"(d[2]), "+f"(d[3])
        : "r"(a[0]), "r"(a[1]), "r"(a[2]), "r"(a[3]), "r"(b[0]), "r"(b[1]));
}
__device__ __forceinline__ void cp_async16(uint32_t saddr, const void* gptr) {
    asm volatile("cp.async.cg.shared.global [%0], [%1], 16;"
                 :: "r"(saddr), "l"(gptr) : "memory");
}
__device__ __forceinline__ void cp_async_commit() {
    asm volatile("cp.async.commit_group;" ::: "memory");
}
__device__ __forceinline__ void cp_async_wait0() {
    asm volatile("cp.async.wait_group 0;" ::: "memory");
}
__device__ __forceinline__ void cp_async_wait1() {
    asm volatile("cp.async.wait_group 1;" ::: "memory");
}
__device__ __forceinline__ unsigned pack2h(float a, float b) {
    __half2 t = __floats2half2_rn(a, b);
    return *reinterpret_cast<unsigned*>(&t);
}

__device__ __forceinline__ int edge_idx(const void* ei, int which, int e) {
    if (g_is64) return (int)((const long long*)ei)[(size_t)which * EE + e];
    return ((const int*)ei)[(size_t)which * EE + e];
}

// ---------------------------------------------------------------- setup
__global__ void detect_init_kernel(const int* __restrict__ ei32) {
    int i = blockIdx.x * blockDim.x + threadIdx.x;
    if (i < NN) { g_deg[i] = 0; g_cnt[i] = 0; }
    if (i == 0) {
        int all_zero = 1;
        for (int j = 0; j < 128; j++)
            if (ei32[2 * j + 1] != 0) { all_zero = 0; break; }
        g_is64 = all_zero;
    }
}
__global__ void count_deg_kernel(const void* __restrict__ ei) {
    int e = blockIdx.x * blockDim.x + threadIdx.x;
    if (e < EE) {
        int d = edge_idx(ei, 1, e);
        if ((unsigned)d < (unsigned)NN) atomicAdd(&g_deg[d], 1);
    }
}

// -------- multi-block exclusive scan of g_deg -> g_rowoff
__global__ void __launch_bounds__(256) scan_partial_kernel() {
    __shared__ int s[256];
    int t = threadIdx.x;
    int idx = blockIdx.x * 256 + t;
    s[t] = (idx < NN) ? g_deg[idx] : 0;
    __syncthreads();
#pragma unroll
    for (int off = 128; off > 0; off >>= 1) {
        if (t < off) s[t] += s[t + off];
        __syncthreads();
    }
    if (t == 0) g_part[blockIdx.x] = s[0];
}
__global__ void __launch_bounds__(256) scan_part_scan_kernel() {
    __shared__ int s[256];
    int t = threadIdx.x;
    int v = (t < SCAN_NB) ? g_part[t] : 0;
    s[t] = v;
    __syncthreads();
#pragma unroll
    for (int off = 1; off < 256; off <<= 1) {
        int u = (t >= off) ? s[t - off] : 0;
        __syncthreads();
        s[t] += u;
        __syncthreads();
    }
    if (t < SCAN_NB) g_part[t] = s[t] - v;  // exclusive
}
__global__ void __launch_bounds__(256) rowoff_kernel() {
    __shared__ int s[256];
    int t = threadIdx.x;
    int idx = blockIdx.x * 256 + t;
    int v = (idx < NN) ? g_deg[idx] : 0;
    s[t] = v;
    __syncthreads();
#pragma unroll
    for (int off = 1; off < 256; off <<= 1) {
        int u = (t >= off) ? s[t - off] : 0;
        __syncthreads();
        s[t] += u;
        __syncthreads();
    }
    if (idx <= NN) g_rowoff[idx] = g_part[blockIdx.x] + (s[t] - v);
}

__global__ void fill_csr_kernel(const void* __restrict__ ei) {
    int e = blockIdx.x * blockDim.x + threadIdx.x;
    if (e >= EE) return;
    int s = edge_idx(ei, 0, e);
    int d = edge_idx(ei, 1, e);
    if ((unsigned)s >= (unsigned)NN || (unsigned)d >= (unsigned)NN) return;
    int pos = g_rowoff[d] + atomicAdd(&g_cnt[d], 1);
    g_csr[pos] = s;
}

// ---------------------------------------------------------------- W converts
__global__ void __launch_bounds__(256) split_W1_kernel(const float* __restrict__ W1) {
    int i = blockIdx.x * blockDim.x + threadIdx.x;
    if (i >= F1 * F2) return;
    __half h = __float2half_rn(W1[i]);
    g_B1h[i] = *reinterpret_cast<uint16_t*>(&h);
}
__global__ void __launch_bounds__(256) split_W2_kernel(const float* __restrict__ W2) {
    int i = blockIdx.x * blockDim.x + threadIdx.x;
    if (i >= F2 * F3) return;
    __half h = __float2half_rn(W2[i]);
    g_B2h[i] = *reinterpret_cast<uint16_t*>(&h);
}

// ---------------------------------------------------------------- GEMM (fp16 mma.sync, single product)
// C[m, n0+n] = rsqrt(deg[m]+1) * sum_k fp16(A[m,k]) * fp16(B[k, n0+n])
// CTA tile 128 x 128, 256 threads, 2 CTAs/SM, BK=32, 3-stage cp.async for B.
#define SA_STRIDE 80
#define GEMM_N 128
#define GEMM_SB (GEMM_N * 2 + 16)      // 272
#define GEMM_AH 0
#define GEMM_BH (128 * SA_STRIDE)      // 10240
#define GEMM_BUFB (GEMM_BH + 32 * GEMM_SB)   // 18944
#define GEMM_SMEM (3 * GEMM_BUFB)            // 56832

template <int K, int BW>
__device__ __forceinline__ void gemm_mma_dev(const float* __restrict__ A,
                                             const uint16_t* __restrict__ Bh,
                                             float* __restrict__ C) {
    constexpr int T = K / 32;

    extern __shared__ char smem[];
    const uint32_t sb = smem_u32(smem);
    const int tid = threadIdx.x;
    const int lane = tid & 31;
    const int wid = tid >> 5;           // 0..7
    const int wm = wid >> 1;            // 0..3  (rows wm*32)
    const int wn = wid & 1;             // 0..1  (cols wn*64)
    const int m0 = blockIdx.y * 128;
    const int n0 = blockIdx.x * GEMM_N;

    float acc[2][8][4];
#pragma unroll
    for (int a = 0; a < 2; a++)
#pragma unroll
        for (int b = 0; b < 8; b++)
#pragma unroll
            for (int c = 0; c < 4; c++) acc[a][b][c] = 0.f;

    float4 pa[4];
    const int ar = tid >> 3, ac = tid & 7;

    auto load_A = [&](int t) {
        const float* xa = A + (size_t)m0 * K + t * 32;
#pragma unroll
        for (int j = 0; j < 4; j++) {
            int row = ar + j * 32;
            pa[j] = (m0 + row < NN)
                        ? *reinterpret_cast<const float4*>(xa + (size_t)row * K + ac * 4)
                        : make_float4(0.f, 0.f, 0.f, 0.f);
        }
    };

    auto issue_B = [&](int t, int buf) {
        const uint16_t* bh = Bh + (size_t)(t * 32) * BW + n0;
        const uint32_t base = sb + buf * GEMM_BUFB;
#pragma unroll
        for (int i = 0; i < 2; i++) {
            int idx = tid + i * 256;
            int k = idx >> 4, c = idx & 15;
            cp_async16(base + GEMM_BH + k * GEMM_SB + c * 16, bh + (size_t)k * BW + c * 8);
        }
        cp_async_commit();
    };

    auto store_A = [&](int buf) {
        char* sbuf = smem + buf * GEMM_BUFB;
#pragma unroll
        for (int j = 0; j < 4; j++) {
            int r = ar + j * 32;
            float4 v = pa[j];
            uint2 hi = make_uint2(pack2h(v.x, v.y), pack2h(v.z, v.w));
            *reinterpret_cast<uint2*>(sbuf + GEMM_AH + r * SA_STRIDE + ac * 8) = hi;
        }
    };

    auto compute = [&](int buf) {
        const uint32_t bufb = sb + buf * GEMM_BUFB;
#pragma unroll
        for (int ks = 0; ks < 2; ks++) {
            uint32_t Ah[2][4];
#pragma unroll
            for (int mi = 0; mi < 2; mi++) {
                uint32_t addr = bufb + GEMM_AH +
                                (wm * 32 + mi * 16 + (lane & 15)) * SA_STRIDE +
                                (ks * 16 + (lane >> 4) * 8) * 2;
                ldsm_x4(Ah[mi][0], Ah[mi][1], Ah[mi][2], Ah[mi][3], addr);
            }
#pragma unroll
            for (int np = 0; np < 4; np++) {
                uint32_t baddr = bufb + GEMM_BH + (ks * 16 + (lane & 15)) * GEMM_SB +
                                 (wn * 64 + np * 16 + (lane >> 4) * 8) * 2;
                uint32_t bh[4];
                ldsm_x4_t(bh[0], bh[1], bh[2], bh[3], baddr);
                mma_f16(acc[0][np * 2 + 0], Ah[0], bh + 0);
                mma_f16(acc[1][np * 2 + 0], Ah[1], bh + 0);
                mma_f16(acc[0][np * 2 + 1], Ah[0], bh + 2);
                mma_f16(acc[1][np * 2 + 1], Ah[1], bh + 2);
            }
        }
    };

    // prologue: stage 0 fully, B(1) in flight, A(1) in regs
    load_A(0);
    issue_B(0, 0);
    store_A(0);
    load_A(1);
    issue_B(1, 1);
    cp_async_wait1();
    __syncthreads();

    int b0 = 0, b1 = 1, b2 = 2;
    for (int t = 0; t < T; t++) {
        if (t + 1 < T) store_A(b1);
        if (t + 2 < T) { load_A(t + 2); issue_B(t + 2, b2); }
        compute(b0);
        if (t + 1 < T) {
            if (t + 2 < T) cp_async_wait1(); else cp_async_wait0();
            __syncthreads();
        }
        int tmp = b0; b0 = b1; b1 = b2; b2 = tmp;
    }

    // epilogue: scale by rsqrt(deg+1), write C
#pragma unroll
    for (int mi = 0; mi < 2; mi++) {
        int r0 = m0 + wm * 32 + mi * 16 + (lane >> 2);
        int r1 = r0 + 8;
        float s0 = (r0 < NN) ? rsqrtf((float)g_deg[r0] + 1.0f) : 0.f;
        float s1 = (r1 < NN) ? rsqrtf((float)g_deg[r1] + 1.0f) : 0.f;
#pragma unroll
        for (int nt = 0; nt < 8; nt++) {
            int col = n0 + wn * 64 + nt * 8 + (lane & 3) * 2;
            if (r0 < NN) {
                float2 v = make_float2(acc[mi][nt][0] * s0, acc[mi][nt][1] * s0);
                *reinterpret_cast<float2*>(C + (size_t)r0 * BW + col) = v;
            }
            if (r1 < NN) {
                float2 v = make_float2(acc[mi][nt][2] * s1, acc[mi][nt][3] * s1);
                *reinterpret_cast<float2*>(C + (size_t)r1 * BW + col) = v;
            }
        }
    }
}

__global__ void __launch_bounds__(256, 2) gemm1_kernel(const float* __restrict__ x) {
    gemm_mma_dev<F1, F2>(x, g_B1h, g_g1);
}
__global__ void __launch_bounds__(256, 2) gemm2_kernel() {
    gemm_mma_dev<F2, F3>(g_h1, g_B2h, g_g2);
}

// ---------------------------------------------------------------- aggregation
// out[d,c] = post( rsqrt(deg[d]+1) * (g[d,c] + sum_{s in CSR[d]} g[s,c]) + bias[c] )
template <int F, bool RELU>
__device__ __forceinline__ void agg_dev(const float* __restrict__ g,
                                        const float* __restrict__ bias,
                                        float* __restrict__ out) {
    __shared__ int s_idx[F];
    int d = blockIdx.x;
    int c = threadIdx.x;
    int start = g_rowoff[d];
    int end = g_rowoff[d + 1];
    float acc = g[(size_t)d * F + c];  // self loop
    for (int base = start; base < end; base += F) {
        int n = min(F, end - base);
        __syncthreads();
        if (c < n) s_idx[c] = g_csr[base + c];
        __syncthreads();
        int i = 0;
        float acc2 = 0.f;
        for (; i + 1 < n; i += 2) {
            acc += g[(size_t)s_idx[i] * F + c];
            acc2 += g[(size_t)s_idx[i + 1] * F + c];
        }
        if (i < n) acc += g[(size_t)s_idx[i] * F + c];
        acc += acc2;
    }
    float v = fmaf(acc, rsqrtf((float)g_deg[d] + 1.0f), bias[c]);
    if (RELU) v = fmaxf(v, 0.f);
    out[(size_t)d * F + c] = v;
}

__global__ void __launch_bounds__(F2) agg1_kernel(const float* __restrict__ b1) {
    agg_dev<F2, true>(g_g1, b1, g_h1);
}
__global__ void __launch_bounds__(F3) agg2_kernel(const float* __restrict__ b2,
                                                  float* __restrict__ out) {
    agg_dev<F3, false>(g_g2, b2, out);
}

// ---------------------------------------------------------------- launch
extern "C" void kernel_launch(void* const* d_in, const int* in_sizes, int n_in,
                              void* d_out, int out_size) {
    const float* x = (const float*)d_in[0];
    const void* ei = d_in[1];
    const float* W1 = (const float*)d_in[2];
    const float* b1 = (const float*)d_in[3];
    const float* W2 = (const float*)d_in[4];
    const float* b2 = (const float*)d_in[5];
    float* out = (float*)d_out;

    cudaFuncSetAttribute(gemm1_kernel,
                         cudaFuncAttributeMaxDynamicSharedMemorySize, GEMM_SMEM);
    cudaFuncSetAttribute(gemm2_kernel,
                         cudaFuncAttributeMaxDynamicSharedMemorySize, GEMM_SMEM);

    // Launch order chosen so gemm1 is the 4th launch (ncu capture slot).
    split_W1_kernel<<<(F1 * F2 + 255) / 256, 256>>>(W1);            // 1
    detect_init_kernel<<<(NN + 255) / 256, 256>>>((const int*)ei);  // 2
    count_deg_kernel<<<(EE + 255) / 256, 256>>>(ei);                // 3
    {
        dim3 grid(F2 / GEMM_N, (NN + 127) / 128);                   // (2, 391)
        gemm1_kernel<<<grid, 256, GEMM_SMEM>>>(x);                  // 4
    }

    // CSR build (independent of gemm1)
    scan_partial_kernel<<<SCAN_NB, 256>>>();
    scan_part_scan_kernel<<<1, 256>>>();
    rowoff_kernel<<<SCAN_NB, 256>>>();
    fill_csr_kernel<<<(EE + 255) / 256, 256>>>(ei);

    agg1_kernel<<<NN, F2>>>(b1);

    split_W2_kernel<<<(F2 * F3 + 255) / 256, 256>>>(W2);
    {
        dim3 grid(F3 / GEMM_N, (NN + 127) / 128);                   // (1, 391)
        gemm2_kernel<<<grid, 256, GEMM_SMEM>>>();
    }
    agg2_kernel<<<NN, F3>>>(b2, out);
}

// round 15
// speedup vs baseline: 1.3482x; 1.1382x over previous
#include <cuda_runtime.h>
#include <cuda_bf16.h>
#include <cuda_fp16.h>
#include <cstdint>

#define NN 50000
#define EE 800000
#define F1 4096
#define F2 256
#define F3 128
#define SCAN_NB ((NN + 255) / 256)

// ---------------------------------------------------------------- scratch
__device__ int   g_is64;
__device__ int   g_deg[NN];
__device__ int   g_cnt[NN];
__device__ int   g_part[SCAN_NB];
__device__ int   g_rowoff[NN + 1];
__device__ int   g_csr[EE];
__device__ uint32_t g_g1[NN * F2 / 2];   // layer-1 dense output, half2 packed
__device__ uint32_t g_h1[NN * F2 / 2];   // relu'd layer-1 output, half2 packed
__device__ float g_g2[NN * F3];          // layer-2 dense output (fp32)
__device__ uint16_t g_B1h[F1 * F2];      // W1 fp16
__device__ uint16_t g_B2h[F2 * F3];      // W2 fp16

// ---------------------------------------------------------------- helpers
__device__ __forceinline__ uint32_t smem_u32(const void* p) {
    uint32_t a;
    asm("{ .reg .u64 t; cvta.to.shared.u64 t, %1; cvt.u32.u64 %0, t; }"
        : "=r"(a) : "l"(p));
    return a;
}
__device__ __forceinline__ void ldsm_x4(uint32_t& r0, uint32_t& r1, uint32_t& r2,
                                        uint32_t& r3, uint32_t addr) {
    asm volatile("ldmatrix.sync.aligned.m8n8.x4.shared.b16 {%0,%1,%2,%3}, [%4];"
                 : "=r"(r0), "=r"(r1), "=r"(r2), "=r"(r3) : "r"(addr));
}
__device__ __forceinline__ void ldsm_x4_t(uint32_t& r0, uint32_t& r1, uint32_t& r2,
                                          uint32_t& r3, uint32_t addr) {
    asm volatile("ldmatrix.sync.aligned.m8n8.x4.trans.shared.b16 {%0,%1,%2,%3}, [%4];"
                 : "=r"(r0), "=r"(r1), "=r"(r2), "=r"(r3) : "r"(addr));
}
__device__ __forceinline__ void mma_f16(float* d, const uint32_t* a,
                                        const uint32_t* b) {
    asm volatile(
        "mma.sync.aligned.m16n8k16.row.col.f32.f16.f16.f32 "
        "{%0,%1,%2,%3}, {%4,%5,%6,%7}, {%8,%9}, {%0,%1,%2,%3};"
        : "+f"(d[0]), "+f"(d[1]), "+f"(d[2]), "+f"(d[3])
        : "r"(a[0]), "r"(a[1]), "r"(a[2]), "r"(a[3]), "r"(b[0]), "r"(b[1]));
}
__device__ __forceinline__ void cp_async16(uint32_t saddr, const void* gptr) {
    asm volatile("cp.async.cg.shared.global [%0], [%1], 16;"
                 :: "r"(saddr), "l"(gptr) : "memory");
}
__device__ __forceinline__ void cp_async_commit() {
    asm volatile("cp.async.commit_group;" ::: "memory");
}
__device__ __forceinline__ void cp_async_wait0() {
    asm volatile("cp.async.wait_group 0;" ::: "memory");
}
__device__ __forceinline__ void cp_async_wait1() {
    asm volatile("cp.async.wait_group 1;" ::: "memory");
}
__device__ __forceinline__ unsigned pack2h(float a, float b) {
    __half2 t = __floats2half2_rn(a, b);
    return *reinterpret_cast<unsigned*>(&t);
}

__device__ __forceinline__ int edge_idx(const void* ei, int which, int e) {
    if (g_is64) return (int)((const long long*)ei)[(size_t)which * EE + e];
    return ((const int*)ei)[(size_t)which * EE + e];
}

// ---------------------------------------------------------------- setup
__global__ void detect_init_kernel(const int* __restrict__ ei32) {
    int i = blockIdx.x * blockDim.x + threadIdx.x;
    if (i < NN) { g_deg[i] = 0; g_cnt[i] = 0; }
    if (i == 0) {
        int all_zero = 1;
        for (int j = 0; j < 128; j++)
            if (ei32[2 * j + 1] != 0) { all_zero = 0; break; }
        g_is64 = all_zero;
    }
}
__global__ void count_deg_kernel(const void* __restrict__ ei) {
    int e = blockIdx.x * blockDim.x + threadIdx.x;
    if (e < EE) {
        int d = edge_idx(ei, 1, e);
        if ((unsigned)d < (unsigned)NN) atomicAdd(&g_deg[d], 1);
    }
}

// -------- multi-block exclusive scan of g_deg -> g_rowoff
__global__ void __launch_bounds__(256) scan_partial_kernel() {
    __shared__ int s[256];
    int t = threadIdx.x;
    int idx = blockIdx.x * 256 + t;
    s[t] = (idx < NN) ? g_deg[idx] : 0;
    __syncthreads();
#pragma unroll
    for (int off = 128; off > 0; off >>= 1) {
        if (t < off) s[t] += s[t + off];
        __syncthreads();
    }
    if (t == 0) g_part[blockIdx.x] = s[0];
}
__global__ void __launch_bounds__(256) scan_part_scan_kernel() {
    __shared__ int s[256];
    int t = threadIdx.x;
    int v = (t < SCAN_NB) ? g_part[t] : 0;
    s[t] = v;
    __syncthreads();
#pragma unroll
    for (int off = 1; off < 256; off <<= 1) {
        int u = (t >= off) ? s[t - off] : 0;
        __syncthreads();
        s[t] += u;
        __syncthreads();
    }
    if (t < SCAN_NB) g_part[t] = s[t] - v;  // exclusive
}
__global__ void __launch_bounds__(256) rowoff_kernel() {
    __shared__ int s[256];
    int t = threadIdx.x;
    int idx = blockIdx.x * 256 + t;
    int v = (idx < NN) ? g_deg[idx] : 0;
    s[t] = v;
    __syncthreads();
#pragma unroll
    for (int off = 1; off < 256; off <<= 1) {
        int u = (t >= off) ? s[t - off] : 0;
        __syncthreads();
        s[t] += u;
        __syncthreads();
    }
    if (idx <= NN) g_rowoff[idx] = g_part[blockIdx.x] + (s[t] - v);
}

__global__ void fill_csr_kernel(const void* __restrict__ ei) {
    int e = blockIdx.x * blockDim.x + threadIdx.x;
    if (e >= EE) return;
    int s = edge_idx(ei, 0, e);
    int d = edge_idx(ei, 1, e);
    if ((unsigned)s >= (unsigned)NN || (unsigned)d >= (unsigned)NN) return;
    int pos = g_rowoff[d] + atomicAdd(&g_cnt[d], 1);
    g_csr[pos] = s;
}

// ---------------------------------------------------------------- W converts
__global__ void __launch_bounds__(256) split_W1_kernel(const float* __restrict__ W1) {
    int i = blockIdx.x * blockDim.x + threadIdx.x;
    if (i >= F1 * F2) return;
    __half h = __float2half_rn(W1[i]);
    g_B1h[i] = *reinterpret_cast<uint16_t*>(&h);
}
__global__ void __launch_bounds__(256) split_W2_kernel(const float* __restrict__ W2) {
    int i = blockIdx.x * blockDim.x + threadIdx.x;
    if (i >= F2 * F3) return;
    __half h = __float2half_rn(W2[i]);
    g_B2h[i] = *reinterpret_cast<uint16_t*>(&h);
}

// ---------------------------------------------------------------- GEMM (fp16 mma.sync, single product)
// C[m, n0+n] = rsqrt(deg[m]+1) * sum_k fp16(A[m,k]) * fp16(B[k, n0+n])
// CTA tile 128 x 128, 256 threads, 2 CTAs/SM, BK=32, 3-stage cp.async for B.
// AHALF: A already fp16 in gmem (pure copy to smem).
// CHALF: C written as packed half2.
#define SA_STRIDE 80
#define GEMM_N 128
#define GEMM_SB (GEMM_N * 2 + 16)      // 272
#define GEMM_AH 0
#define GEMM_BH (128 * SA_STRIDE)      // 10240
#define GEMM_BUFB (GEMM_BH + 32 * GEMM_SB)   // 18944
#define GEMM_SMEM (3 * GEMM_BUFB)            // 56832

template <int K, int BW, bool AHALF, bool CHALF>
__device__ __forceinline__ void gemm_mma_dev(const void* __restrict__ Av,
                                             const uint16_t* __restrict__ Bh,
                                             void* __restrict__ Cv) {
    constexpr int T = K / 32;

    extern __shared__ char smem[];
    const uint32_t sb = smem_u32(smem);
    const int tid = threadIdx.x;
    const int lane = tid & 31;
    const int wid = tid >> 5;           // 0..7
    const int wm = wid >> 1;            // 0..3  (rows wm*32)
    const int wn = wid & 1;             // 0..1  (cols wn*64)
    const int m0 = blockIdx.y * 128;
    const int n0 = blockIdx.x * GEMM_N;

    float acc[2][8][4];
#pragma unroll
    for (int a = 0; a < 2; a++)
#pragma unroll
        for (int b = 0; b < 8; b++)
#pragma unroll
            for (int c = 0; c < 4; c++) acc[a][b][c] = 0.f;

    float4 pa[4];
    uint2 pah[4];
    const int ar = tid >> 3, ac = tid & 7;

    auto load_A = [&](int t) {
#pragma unroll
        for (int j = 0; j < 4; j++) {
            int row = ar + j * 32;
            bool ok = (m0 + row < NN);
            if (AHALF) {
                const uint16_t* xa = (const uint16_t*)Av + (size_t)m0 * K + t * 32;
                pah[j] = ok ? *reinterpret_cast<const uint2*>(xa + (size_t)row * K + ac * 4)
                            : make_uint2(0u, 0u);
            } else {
                const float* xa = (const float*)Av + (size_t)m0 * K + t * 32;
                pa[j] = ok ? *reinterpret_cast<const float4*>(xa + (size_t)row * K + ac * 4)
                           : make_float4(0.f, 0.f, 0.f, 0.f);
            }
        }
    };

    auto issue_B = [&](int t, int buf) {
        const uint16_t* bh = Bh + (size_t)(t * 32) * BW + n0;
        const uint32_t base = sb + buf * GEMM_BUFB;
#pragma unroll
        for (int i = 0; i < 2; i++) {
            int idx = tid + i * 256;
            int k = idx >> 4, c = idx & 15;
            cp_async16(base + GEMM_BH + k * GEMM_SB + c * 16, bh + (size_t)k * BW + c * 8);
        }
        cp_async_commit();
    };

    auto store_A = [&](int buf) {
        char* sbuf = smem + buf * GEMM_BUFB;
#pragma unroll
        for (int j = 0; j < 4; j++) {
            int r = ar + j * 32;
            uint2 hi;
            if (AHALF) {
                hi = pah[j];
            } else {
                float4 v = pa[j];
                hi = make_uint2(pack2h(v.x, v.y), pack2h(v.z, v.w));
            }
            *reinterpret_cast<uint2*>(sbuf + GEMM_AH + r * SA_STRIDE + ac * 8) = hi;
        }
    };

    auto compute = [&](int buf) {
        const uint32_t bufb = sb + buf * GEMM_BUFB;
#pragma unroll
        for (int ks = 0; ks < 2; ks++) {
            uint32_t Ah[2][4];
#pragma unroll
            for (int mi = 0; mi < 2; mi++) {
                uint32_t addr = bufb + GEMM_AH +
                                (wm * 32 + mi * 16 + (lane & 15)) * SA_STRIDE +
                                (ks * 16 + (lane >> 4) * 8) * 2;
                ldsm_x4(Ah[mi][0], Ah[mi][1], Ah[mi][2], Ah[mi][3], addr);
            }
#pragma unroll
            for (int np = 0; np < 4; np++) {
                uint32_t baddr = bufb + GEMM_BH + (ks * 16 + (lane & 15)) * GEMM_SB +
                                 (wn * 64 + np * 16 + (lane >> 4) * 8) * 2;
                uint32_t bh[4];
                ldsm_x4_t(bh[0], bh[1], bh[2], bh[3], baddr);
                mma_f16(acc[0][np * 2 + 0], Ah[0], bh + 0);
                mma_f16(acc[1][np * 2 + 0], Ah[1], bh + 0);
                mma_f16(acc[0][np * 2 + 1], Ah[0], bh + 2);
                mma_f16(acc[1][np * 2 + 1], Ah[1], bh + 2);
            }
        }
    };

    // prologue: stage 0 fully, B(1) in flight, A(1) in regs
    load_A(0);
    issue_B(0, 0);
    store_A(0);
    load_A(1);
    issue_B(1, 1);
    cp_async_wait1();
    __syncthreads();

    int b0 = 0, b1 = 1, b2 = 2;
    for (int t = 0; t < T; t++) {
        if (t + 1 < T) store_A(b1);
        if (t + 2 < T) { load_A(t + 2); issue_B(t + 2, b2); }
        compute(b0);
        if (t + 1 < T) {
            if (t + 2 < T) cp_async_wait1(); else cp_async_wait0();
            __syncthreads();
        }
        int tmp = b0; b0 = b1; b1 = b2; b2 = tmp;
    }

    // epilogue: scale by rsqrt(deg+1), write C
#pragma unroll
    for (int mi = 0; mi < 2; mi++) {
        int r0 = m0 + wm * 32 + mi * 16 + (lane >> 2);
        int r1 = r0 + 8;
        float s0 = (r0 < NN) ? rsqrtf((float)g_deg[r0] + 1.0f) : 0.f;
        float s1 = (r1 < NN) ? rsqrtf((float)g_deg[r1] + 1.0f) : 0.f;
#pragma unroll
        for (int nt = 0; nt < 8; nt++) {
            int col = n0 + wn * 64 + nt * 8 + (lane & 3) * 2;
            if (CHALF) {
                uint32_t* Ch = (uint32_t*)Cv;
                if (r0 < NN)
                    Ch[((size_t)r0 * BW + col) >> 1] =
                        pack2h(acc[mi][nt][0] * s0, acc[mi][nt][1] * s0);
                if (r1 < NN)
                    Ch[((size_t)r1 * BW + col) >> 1] =
                        pack2h(acc[mi][nt][2] * s1, acc[mi][nt][3] * s1);
            } else {
                float* Cf = (float*)Cv;
                if (r0 < NN) {
                    float2 v = make_float2(acc[mi][nt][0] * s0, acc[mi][nt][1] * s0);
                    *reinterpret_cast<float2*>(Cf + (size_t)r0 * BW + col) = v;
                }
                if (r1 < NN) {
                    float2 v = make_float2(acc[mi][nt][2] * s1, acc[mi][nt][3] * s1);
                    *reinterpret_cast<float2*>(Cf + (size_t)r1 * BW + col) = v;
                }
            }
        }
    }
}

__global__ void __launch_bounds__(256, 2) gemm1_kernel(const float* __restrict__ x) {
    gemm_mma_dev<F1, F2, false, true>(x, g_B1h, g_g1);
}
__global__ void __launch_bounds__(256, 2) gemm2_kernel() {
    gemm_mma_dev<F2, F3, true, false>(g_h1, g_B2h, g_g2);
}

// ---------------------------------------------------------------- aggregation
// Layer 1 (half2 in / half2 out):
// h1[d,:] = relu( rsqrt(deg+1) * (g1[d,:] + sum_{s} g1[s,:]) + b1 )
__global__ void __launch_bounds__(F2 / 2) agg1_kernel(const float* __restrict__ b1) {
    __shared__ int s_idx[F2 / 2];
    const __half2* g = reinterpret_cast<const __half2*>(g_g1);
    int d = blockIdx.x;
    int c = threadIdx.x;                 // half2 column 0..127
    int start = g_rowoff[d];
    int end = g_rowoff[d + 1];

    float2 acc = __half22float2(g[(size_t)d * (F2 / 2) + c]);   // self loop
    float2 acc2 = make_float2(0.f, 0.f);
    for (int base = start; base < end; base += F2 / 2) {
        int n = min(F2 / 2, end - base);
        __syncthreads();
        if (c < n) s_idx[c] = g_csr[base + c];
        __syncthreads();
        int i = 0;
        for (; i + 1 < n; i += 2) {
            float2 f0 = __half22float2(g[(size_t)s_idx[i] * (F2 / 2) + c]);
            float2 f1 = __half22float2(g[(size_t)s_idx[i + 1] * (F2 / 2) + c]);
            acc.x += f0.x; acc.y += f0.y;
            acc2.x += f1.x; acc2.y += f1.y;
        }
        if (i < n) {
            float2 f0 = __half22float2(g[(size_t)s_idx[i] * (F2 / 2) + c]);
            acc.x += f0.x; acc.y += f0.y;
        }
    }
    acc.x += acc2.x; acc.y += acc2.y;

    float s = rsqrtf((float)g_deg[d] + 1.0f);
    float2 bb = *reinterpret_cast<const float2*>(b1 + c * 2);
    float rx = fmaxf(fmaf(acc.x, s, bb.x), 0.f);
    float ry = fmaxf(fmaf(acc.y, s, bb.y), 0.f);
    reinterpret_cast<__half2*>(g_h1)[(size_t)d * (F2 / 2) + c] = __floats2half2_rn(rx, ry);
}

// Layer 2 (fp32): out[d,c] = rsqrt(deg+1)*(g2[d,c] + sum g2[s,c]) + b2[c]
__global__ void __launch_bounds__(F3) agg2_kernel(const float* __restrict__ b2,
                                                  float* __restrict__ out) {
    __shared__ int s_idx[F3];
    int d = blockIdx.x;
    int c = threadIdx.x;
    int start = g_rowoff[d];
    int end = g_rowoff[d + 1];
    float acc = g_g2[(size_t)d * F3 + c];  // self loop
    for (int base = start; base < end; base += F3) {
        int n = min(F3, end - base);
        __syncthreads();
        if (c < n) s_idx[c] = g_csr[base + c];
        __syncthreads();
        int i = 0;
        float acc2 = 0.f;
        for (; i + 1 < n; i += 2) {
            acc += g_g2[(size_t)s_idx[i] * F3 + c];
            acc2 += g_g2[(size_t)s_idx[i + 1] * F3 + c];
        }
        if (i < n) acc += g_g2[(size_t)s_idx[i] * F3 + c];
        acc += acc2;
    }
    float v = fmaf(acc, rsqrtf((float)g_deg[d] + 1.0f), b2[c]);
    out[(size_t)d * F3 + c] = v;
}

// ---------------------------------------------------------------- launch
extern "C" void kernel_launch(void* const* d_in, const int* in_sizes, int n_in,
                              void* d_out, int out_size) {
    const float* x = (const float*)d_in[0];
    const void* ei = d_in[1];
    const float* W1 = (const float*)d_in[2];
    const float* b1 = (const float*)d_in[3];
    const float* W2 = (const float*)d_in[4];
    const float* b2 = (const float*)d_in[5];
    float* out = (float*)d_out;

    cudaFuncSetAttribute(gemm1_kernel,
                         cudaFuncAttributeMaxDynamicSharedMemorySize, GEMM_SMEM);
    cudaFuncSetAttribute(gemm2_kernel,
                         cudaFuncAttributeMaxDynamicSharedMemorySize, GEMM_SMEM);

    // Launch order chosen so gemm1 is the 4th launch (ncu capture slot).
    split_W1_kernel<<<(F1 * F2 + 255) / 256, 256>>>(W1);            // 1
    detect_init_kernel<<<(NN + 255) / 256, 256>>>((const int*)ei);  // 2
    count_deg_kernel<<<(EE + 255) / 256, 256>>>(ei);                // 3
    {
        dim3 grid(F2 / GEMM_N, (NN + 127) / 128);                   // (2, 391)
        gemm1_kernel<<<grid, 256, GEMM_SMEM>>>(x);                  // 4
    }

    // CSR build (independent of gemm1)
    scan_partial_kernel<<<SCAN_NB, 256>>>();
    scan_part_scan_kernel<<<1, 256>>>();
    rowoff_kernel<<<SCAN_NB, 256>>>();
    fill_csr_kernel<<<(EE + 255) / 256, 256>>>(ei);

    agg1_kernel<<<NN, F2 / 2>>>(b1);

    split_W2_kernel<<<(F2 * F3 + 255) / 256, 256>>>(W2);
    {
        dim3 grid(F3 / GEMM_N, (NN + 127) / 128);                   // (1, 391)
        gemm2_kernel<<<grid, 256, GEMM_SMEM>>>();
    }
    agg2_kernel<<<NN, F3>>>(b2, out);
}

// round 16
// speedup vs baseline: 1.4244x; 1.0565x over previous
#include <cuda_runtime.h>
#include <cuda_bf16.h>
#include <cuda_fp16.h>
#include <cstdint>

#define NN 50000
#define EE 800000
#define F1 4096
#define F2 256
#define F3 128
#define SCAN_NB ((NN + 255) / 256)

// ---------------------------------------------------------------- scratch
__device__ int   g_is64;
__device__ int   g_deg[NN];
__device__ int   g_cnt[NN];
__device__ int   g_part[SCAN_NB];
__device__ int   g_rowoff[NN + 1];
__device__ int   g_csr[EE];
__device__ uint32_t g_g1[NN * F2 / 2];   // layer-1 dense output, half2 packed
__device__ uint32_t g_h1[NN * F2 / 2];   // relu'd layer-1 output, half2 packed
__device__ uint32_t g_g2[NN * F3 / 2];   // layer-2 dense output, half2 packed
__device__ uint16_t g_B1h[F1 * F2];      // W1 fp16
__device__ uint16_t g_B2h[F2 * F3];      // W2 fp16

// ---------------------------------------------------------------- helpers
__device__ __forceinline__ uint32_t smem_u32(const void* p) {
    uint32_t a;
    asm("{ .reg .u64 t; cvta.to.shared.u64 t, %1; cvt.u32.u64 %0, t; }"
        : "=r"(a) : "l"(p));
    return a;
}
__device__ __forceinline__ void ldsm_x4(uint32_t& r0, uint32_t& r1, uint32_t& r2,
                                        uint32_t& r3, uint32_t addr) {
    asm volatile("ldmatrix.sync.aligned.m8n8.x4.shared.b16 {%0,%1,%2,%3}, [%4];"
                 : "=r"(r0), "=r"(r1), "=r"(r2), "=r"(r3) : "r"(addr));
}
__device__ __forceinline__ void ldsm_x4_t(uint32_t& r0, uint32_t& r1, uint32_t& r2,
                                          uint32_t& r3, uint32_t addr) {
    asm volatile("ldmatrix.sync.aligned.m8n8.x4.trans.shared.b16 {%0,%1,%2,%3}, [%4];"
                 : "=r"(r0), "=r"(r1), "=r"(r2), "=r"(r3) : "r"(addr));
}
__device__ __forceinline__ void mma_f16(float* d, const uint32_t* a,
                                        const uint32_t* b) {
    asm volatile(
        "mma.sync.aligned.m16n8k16.row.col.f32.f16.f16.f32 "
        "{%0,%1,%2,%3}, {%4,%5,%6,%7}, {%8,%9}, {%0,%1,%2,%3};"
        : "+f"(d[0]), "+f"(d[1]), "+f"(d[2]), "+f"(d[3])
        : "r"(a[0]), "r"(a[1]), "r"(a[2]), "r"(a[3]), "r"(b[0]), "r"(b[1]));
}
__device__ __forceinline__ void cp_async16(uint32_t saddr, const void* gptr) {
    asm volatile("cp.async.cg.shared.global [%0], [%1], 16;"
                 :: "r"(saddr), "l"(gptr) : "memory");
}
__device__ __forceinline__ void cp_async_commit() {
    asm volatile("cp.async.commit_group;" ::: "memory");
}
__device__ __forceinline__ void cp_async_wait0() {
    asm volatile("cp.async.wait_group 0;" ::: "memory");
}
__device__ __forceinline__ void cp_async_wait1() {
    asm volatile("cp.async.wait_group 1;" ::: "memory");
}
__device__ __forceinline__ unsigned pack2h(float a, float b) {
    __half2 t = __floats2half2_rn(a, b);
    return *reinterpret_cast<unsigned*>(&t);
}

__device__ __forceinline__ int edge_idx(const void* ei, int which, int e) {
    if (g_is64) return (int)((const long long*)ei)[(size_t)which * EE + e];
    return ((const int*)ei)[(size_t)which * EE + e];
}

// ---------------------------------------------------------------- setup
// Fused: zero deg/cnt + PARALLEL dtype probe (block 0, 128 lanes + shared OR).
__global__ void detect_init_kernel(const int* __restrict__ ei32) {
    __shared__ int nz;
    int i = blockIdx.x * blockDim.x + threadIdx.x;
    if (blockIdx.x == 0 && threadIdx.x == 0) nz = 0;
    if (blockIdx.x == 0) __syncthreads();
    if (i < NN) { g_deg[i] = 0; g_cnt[i] = 0; }
    if (blockIdx.x == 0) {
        if (threadIdx.x < 128 && ei32[2 * threadIdx.x + 1] != 0) atomicOr(&nz, 1);
        __syncthreads();
        if (threadIdx.x == 0) g_is64 = nz ? 0 : 1;
    }
}
__global__ void count_deg_kernel(const void* __restrict__ ei) {
    int e = blockIdx.x * blockDim.x + threadIdx.x;
    if (e < EE) {
        int d = edge_idx(ei, 1, e);
        if ((unsigned)d < (unsigned)NN) atomicAdd(&g_deg[d], 1);
    }
}

// -------- multi-block exclusive scan of g_deg -> g_rowoff
__global__ void __launch_bounds__(256) scan_partial_kernel() {
    __shared__ int s[256];
    int t = threadIdx.x;
    int idx = blockIdx.x * 256 + t;
    s[t] = (idx < NN) ? g_deg[idx] : 0;
    __syncthreads();
#pragma unroll
    for (int off = 128; off > 0; off >>= 1) {
        if (t < off) s[t] += s[t + off];
        __syncthreads();
    }
    if (t == 0) g_part[blockIdx.x] = s[0];
}
__global__ void __launch_bounds__(256) scan_part_scan_kernel() {
    __shared__ int s[256];
    int t = threadIdx.x;
    int v = (t < SCAN_NB) ? g_part[t] : 0;
    s[t] = v;
    __syncthreads();
#pragma unroll
    for (int off = 1; off < 256; off <<= 1) {
        int u = (t >= off) ? s[t - off] : 0;
        __syncthreads();
        s[t] += u;
        __syncthreads();
    }
    if (t < SCAN_NB) g_part[t] = s[t] - v;  // exclusive
}
__global__ void __launch_bounds__(256) rowoff_kernel() {
    __shared__ int s[256];
    int t = threadIdx.x;
    int idx = blockIdx.x * 256 + t;
    int v = (idx < NN) ? g_deg[idx] : 0;
    s[t] = v;
    __syncthreads();
#pragma unroll
    for (int off = 1; off < 256; off <<= 1) {
        int u = (t >= off) ? s[t - off] : 0;
        __syncthreads();
        s[t] += u;
        __syncthreads();
    }
    if (idx <= NN) g_rowoff[idx] = g_part[blockIdx.x] + (s[t] - v);
}

__global__ void fill_csr_kernel(const void* __restrict__ ei) {
    int e = blockIdx.x * blockDim.x + threadIdx.x;
    if (e >= EE) return;
    int s = edge_idx(ei, 0, e);
    int d = edge_idx(ei, 1, e);
    if ((unsigned)s >= (unsigned)NN || (unsigned)d >= (unsigned)NN) return;
    int pos = g_rowoff[d] + atomicAdd(&g_cnt[d], 1);
    g_csr[pos] = s;
}

// ---------------------------------------------------------------- W converts
__global__ void __launch_bounds__(256) split_W1_kernel(const float* __restrict__ W1) {
    int i = blockIdx.x * blockDim.x + threadIdx.x;
    if (i >= F1 * F2) return;
    __half h = __float2half_rn(W1[i]);
    g_B1h[i] = *reinterpret_cast<uint16_t*>(&h);
}
__global__ void __launch_bounds__(256) split_W2_kernel(const float* __restrict__ W2) {
    int i = blockIdx.x * blockDim.x + threadIdx.x;
    if (i >= F2 * F3) return;
    __half h = __float2half_rn(W2[i]);
    g_B2h[i] = *reinterpret_cast<uint16_t*>(&h);
}

// ---------------------------------------------------------------- GEMM (fp16 mma.sync, single product)
// C[m, n0+n] = rsqrt(deg[m]+1) * sum_k fp16(A[m,k]) * fp16(B[k, n0+n])
// CTA tile 128 x 128, 256 threads, 2 CTAs/SM, BK=32, 3-stage cp.async for B.
// AHALF: A already fp16 in gmem (pure copy to smem).
// CHALF: C written as packed half2.
#define SA_STRIDE 80
#define GEMM_N 128
#define GEMM_SB (GEMM_N * 2 + 16)      // 272
#define GEMM_AH 0
#define GEMM_BH (128 * SA_STRIDE)      // 10240
#define GEMM_BUFB (GEMM_BH + 32 * GEMM_SB)   // 18944
#define GEMM_SMEM (3 * GEMM_BUFB)            // 56832

template <int K, int BW, bool AHALF, bool CHALF>
__device__ __forceinline__ void gemm_mma_dev(const void* __restrict__ Av,
                                             const uint16_t* __restrict__ Bh,
                                             void* __restrict__ Cv) {
    constexpr int T = K / 32;

    extern __shared__ char smem[];
    const uint32_t sb = smem_u32(smem);
    const int tid = threadIdx.x;
    const int lane = tid & 31;
    const int wid = tid >> 5;           // 0..7
    const int wm = wid >> 1;            // 0..3  (rows wm*32)
    const int wn = wid & 1;             // 0..1  (cols wn*64)
    const int m0 = blockIdx.y * 128;
    const int n0 = blockIdx.x * GEMM_N;

    float acc[2][8][4];
#pragma unroll
    for (int a = 0; a < 2; a++)
#pragma unroll
        for (int b = 0; b < 8; b++)
#pragma unroll
            for (int c = 0; c < 4; c++) acc[a][b][c] = 0.f;

    float4 pa[4];
    uint2 pah[4];
    const int ar = tid >> 3, ac = tid & 7;

    auto load_A = [&](int t) {
#pragma unroll
        for (int j = 0; j < 4; j++) {
            int row = ar + j * 32;
            bool ok = (m0 + row < NN);
            if (AHALF) {
                const uint16_t* xa = (const uint16_t*)Av + (size_t)m0 * K + t * 32;
                pah[j] = ok ? *reinterpret_cast<const uint2*>(xa + (size_t)row * K + ac * 4)
                            : make_uint2(0u, 0u);
            } else {
                const float* xa = (const float*)Av + (size_t)m0 * K + t * 32;
                pa[j] = ok ? *reinterpret_cast<const float4*>(xa + (size_t)row * K + ac * 4)
                           : make_float4(0.f, 0.f, 0.f, 0.f);
            }
        }
    };

    auto issue_B = [&](int t, int buf) {
        const uint16_t* bh = Bh + (size_t)(t * 32) * BW + n0;
        const uint32_t base = sb + buf * GEMM_BUFB;
#pragma unroll
        for (int i = 0; i < 2; i++) {
            int idx = tid + i * 256;
            int k = idx >> 4, c = idx & 15;
            cp_async16(base + GEMM_BH + k * GEMM_SB + c * 16, bh + (size_t)k * BW + c * 8);
        }
        cp_async_commit();
    };

    auto store_A = [&](int buf) {
        char* sbuf = smem + buf * GEMM_BUFB;
#pragma unroll
        for (int j = 0; j < 4; j++) {
            int r = ar + j * 32;
            uint2 hi;
            if (AHALF) {
                hi = pah[j];
            } else {
                float4 v = pa[j];
                hi = make_uint2(pack2h(v.x, v.y), pack2h(v.z, v.w));
            }
            *reinterpret_cast<uint2*>(sbuf + GEMM_AH + r * SA_STRIDE + ac * 8) = hi;
        }
    };

    auto compute = [&](int buf) {
        const uint32_t bufb = sb + buf * GEMM_BUFB;
#pragma unroll
        for (int ks = 0; ks < 2; ks++) {
            uint32_t Ah[2][4];
#pragma unroll
            for (int mi = 0; mi < 2; mi++) {
                uint32_t addr = bufb + GEMM_AH +
                                (wm * 32 + mi * 16 + (lane & 15)) * SA_STRIDE +
                                (ks * 16 + (lane >> 4) * 8) * 2;
                ldsm_x4(Ah[mi][0], Ah[mi][1], Ah[mi][2], Ah[mi][3], addr);
            }
#pragma unroll
            for (int np = 0; np < 4; np++) {
                uint32_t baddr = bufb + GEMM_BH + (ks * 16 + (lane & 15)) * GEMM_SB +
                                 (wn * 64 + np * 16 + (lane >> 4) * 8) * 2;
                uint32_t bh[4];
                ldsm_x4_t(bh[0], bh[1], bh[2], bh[3], baddr);
                mma_f16(acc[0][np * 2 + 0], Ah[0], bh + 0);
                mma_f16(acc[1][np * 2 + 0], Ah[1], bh + 0);
                mma_f16(acc[0][np * 2 + 1], Ah[0], bh + 2);
                mma_f16(acc[1][np * 2 + 1], Ah[1], bh + 2);
            }
        }
    };

    // prologue: stage 0 fully, B(1) in flight, A(1) in regs
    load_A(0);
    issue_B(0, 0);
    store_A(0);
    load_A(1);
    issue_B(1, 1);
    cp_async_wait1();
    __syncthreads();

    int b0 = 0, b1 = 1, b2 = 2;
    for (int t = 0; t < T; t++) {
        if (t + 1 < T) store_A(b1);
        if (t + 2 < T) { load_A(t + 2); issue_B(t + 2, b2); }
        compute(b0);
        if (t + 1 < T) {
            if (t + 2 < T) cp_async_wait1(); else cp_async_wait0();
            __syncthreads();
        }
        int tmp = b0; b0 = b1; b1 = b2; b2 = tmp;
    }

    // epilogue: scale by rsqrt(deg+1), write C
#pragma unroll
    for (int mi = 0; mi < 2; mi++) {
        int r0 = m0 + wm * 32 + mi * 16 + (lane >> 2);
        int r1 = r0 + 8;
        float s0 = (r0 < NN) ? rsqrtf((float)g_deg[r0] + 1.0f) : 0.f;
        float s1 = (r1 < NN) ? rsqrtf((float)g_deg[r1] + 1.0f) : 0.f;
#pragma unroll
        for (int nt = 0; nt < 8; nt++) {
            int col = n0 + wn * 64 + nt * 8 + (lane & 3) * 2;
            if (CHALF) {
                uint32_t* Ch = (uint32_t*)Cv;
                if (r0 < NN)
                    Ch[((size_t)r0 * BW + col) >> 1] =
                        pack2h(acc[mi][nt][0] * s0, acc[mi][nt][1] * s0);
                if (r1 < NN)
                    Ch[((size_t)r1 * BW + col) >> 1] =
                        pack2h(acc[mi][nt][2] * s1, acc[mi][nt][3] * s1);
            } else {
                float* Cf = (float*)Cv;
                if (r0 < NN) {
                    float2 v = make_float2(acc[mi][nt][0] * s0, acc[mi][nt][1] * s0);
                    *reinterpret_cast<float2*>(Cf + (size_t)r0 * BW + col) = v;
                }
                if (r1 < NN) {
                    float2 v = make_float2(acc[mi][nt][2] * s1, acc[mi][nt][3] * s1);
                    *reinterpret_cast<float2*>(Cf + (size_t)r1 * BW + col) = v;
                }
            }
        }
    }
}

__global__ void __launch_bounds__(256, 2) gemm1_kernel(const float* __restrict__ x) {
    gemm_mma_dev<F1, F2, false, true>(x, g_B1h, g_g1);
}
__global__ void __launch_bounds__(256, 2) gemm2_kernel() {
    gemm_mma_dev<F2, F3, true, true>(g_h1, g_B2h, g_g2);
}

// ---------------------------------------------------------------- aggregation
// Layer 1 (half2 in / half2 out):
// h1[d,:] = relu( rsqrt(deg+1) * (g1[d,:] + sum_{s} g1[s,:]) + b1 )
__global__ void __launch_bounds__(F2 / 2) agg1_kernel(const float* __restrict__ b1) {
    __shared__ int s_idx[F2 / 2];
    const __half2* g = reinterpret_cast<const __half2*>(g_g1);
    int d = blockIdx.x;
    int c = threadIdx.x;                 // half2 column 0..127
    int start = g_rowoff[d];
    int end = g_rowoff[d + 1];

    float2 acc = __half22float2(g[(size_t)d * (F2 / 2) + c]);   // self loop
    float2 acc2 = make_float2(0.f, 0.f);
    for (int base = start; base < end; base += F2 / 2) {
        int n = min(F2 / 2, end - base);
        __syncthreads();
        if (c < n) s_idx[c] = g_csr[base + c];
        __syncthreads();
        int i = 0;
        for (; i + 1 < n; i += 2) {
            float2 f0 = __half22float2(g[(size_t)s_idx[i] * (F2 / 2) + c]);
            float2 f1 = __half22float2(g[(size_t)s_idx[i + 1] * (F2 / 2) + c]);
            acc.x += f0.x; acc.y += f0.y;
            acc2.x += f1.x; acc2.y += f1.y;
        }
        if (i < n) {
            float2 f0 = __half22float2(g[(size_t)s_idx[i] * (F2 / 2) + c]);
            acc.x += f0.x; acc.y += f0.y;
        }
    }
    acc.x += acc2.x; acc.y += acc2.y;

    float s = rsqrtf((float)g_deg[d] + 1.0f);
    float2 bb = *reinterpret_cast<const float2*>(b1 + c * 2);
    float rx = fmaxf(fmaf(acc.x, s, bb.x), 0.f);
    float ry = fmaxf(fmaf(acc.y, s, bb.y), 0.f);
    reinterpret_cast<__half2*>(g_h1)[(size_t)d * (F2 / 2) + c] = __floats2half2_rn(rx, ry);
}

// Layer 2 (half2 in / fp32 out):
// out[d,:] = rsqrt(deg+1) * (g2[d,:] + sum_{s} g2[s,:]) + b2
__global__ void __launch_bounds__(F3 / 2) agg2_kernel(const float* __restrict__ b2,
                                                      float* __restrict__ out) {
    __shared__ int s_idx[F3 / 2];
    const __half2* g = reinterpret_cast<const __half2*>(g_g2);
    int d = blockIdx.x;
    int c = threadIdx.x;                 // half2 column 0..63
    int start = g_rowoff[d];
    int end = g_rowoff[d + 1];

    float2 acc = __half22float2(g[(size_t)d * (F3 / 2) + c]);   // self loop
    float2 acc2 = make_float2(0.f, 0.f);
    for (int base = start; base < end; base += F3 / 2) {
        int n = min(F3 / 2, end - base);
        __syncthreads();
        if (c < n) s_idx[c] = g_csr[base + c];
        __syncthreads();
        int i = 0;
        for (; i + 1 < n; i += 2) {
            float2 f0 = __half22float2(g[(size_t)s_idx[i] * (F3 / 2) + c]);
            float2 f1 = __half22float2(g[(size_t)s_idx[i + 1] * (F3 / 2) + c]);
            acc.x += f0.x; acc.y += f0.y;
            acc2.x += f1.x; acc2.y += f1.y;
        }
        if (i < n) {
            float2 f0 = __half22float2(g[(size_t)s_idx[i] * (F3 / 2) + c]);
            acc.x += f0.x; acc.y += f0.y;
        }
    }
    acc.x += acc2.x; acc.y += acc2.y;

    float s = rsqrtf((float)g_deg[d] + 1.0f);
    float2 bb = *reinterpret_cast<const float2*>(b2 + c * 2);
    float2 r;
    r.x = fmaf(acc.x, s, bb.x);
    r.y = fmaf(acc.y, s, bb.y);
    *reinterpret_cast<float2*>(out + (size_t)d * F3 + c * 2) = r;
}

// ---------------------------------------------------------------- launch
extern "C" void kernel_launch(void* const* d_in, const int* in_sizes, int n_in,
                              void* d_out, int out_size) {
    const float* x = (const float*)d_in[0];
    const void* ei = d_in[1];
    const float* W1 = (const float*)d_in[2];
    const float* b1 = (const float*)d_in[3];
    const float* W2 = (const float*)d_in[4];
    const float* b2 = (const float*)d_in[5];
    float* out = (float*)d_out;

    cudaFuncSetAttribute(gemm1_kernel,
                         cudaFuncAttributeMaxDynamicSharedMemorySize, GEMM_SMEM);
    cudaFuncSetAttribute(gemm2_kernel,
                         cudaFuncAttributeMaxDynamicSharedMemorySize, GEMM_SMEM);

    // Launch order chosen so gemm1 is the 4th launch (ncu capture slot).
    split_W1_kernel<<<(F1 * F2 + 255) / 256, 256>>>(W1);            // 1
    detect_init_kernel<<<(NN + 255) / 256, 256>>>((const int*)ei);  // 2
    count_deg_kernel<<<(EE + 255) / 256, 256>>>(ei);                // 3
    {
        dim3 grid(F2 / GEMM_N, (NN + 127) / 128);                   // (2, 391)
        gemm1_kernel<<<grid, 256, GEMM_SMEM>>>(x);                  // 4
    }

    // CSR build (independent of gemm1)
    scan_partial_kernel<<<SCAN_NB, 256>>>();
    scan_part_scan_kernel<<<1, 256>>>();
    rowoff_kernel<<<SCAN_NB, 256>>>();
    fill_csr_kernel<<<(EE + 255) / 256, 256>>>(ei);

    agg1_kernel<<<NN, F2 / 2>>>(b1);

    split_W2_kernel<<<(F2 * F3 + 255) / 256, 256>>>(W2);
    {
        dim3 grid(F3 / GEMM_N, (NN + 127) / 128);                   // (1, 391)
        gemm2_kernel<<<grid, 256, GEMM_SMEM>>>();
    }
    agg2_kernel<<<NN, F3 / 2>>>(b2, out);
}

// round 17
// speedup vs baseline: 1.4697x; 1.0319x over previous
#include <cuda_runtime.h>
#include <cuda_bf16.h>
#include <cuda_fp16.h>
#include <cstdint>

#define NN 50000
#define EE 800000
#define F1 4096
#define F2 256
#define F3 128
#define SCAN_NB ((NN + 255) / 256)

// ---------------------------------------------------------------- scratch
__device__ int   g_is64;
__device__ int   g_deg[NN];
__device__ int   g_cnt[NN];
__device__ int   g_part[SCAN_NB];
__device__ int   g_rowoff[NN + 1];
__device__ int   g_csr[EE];
__device__ uint32_t g_g1[NN * F2 / 2];   // layer-1 dense output, half2 packed
__device__ uint32_t g_h1[NN * F2 / 2];   // relu'd layer-1 output, half2 packed
__device__ uint32_t g_g2[NN * F3 / 2];   // layer-2 dense output, half2 packed
__device__ uint16_t g_B1h[F1 * F2];      // W1 fp16
__device__ uint16_t g_B2h[F2 * F3];      // W2 fp16

// ---------------------------------------------------------------- helpers
__device__ __forceinline__ uint32_t smem_u32(const void* p) {
    uint32_t a;
    asm("{ .reg .u64 t; cvta.to.shared.u64 t, %1; cvt.u32.u64 %0, t; }"
        : "=r"(a) : "l"(p));
    return a;
}
__device__ __forceinline__ void ldsm_x4(uint32_t& r0, uint32_t& r1, uint32_t& r2,
                                        uint32_t& r3, uint32_t addr) {
    asm volatile("ldmatrix.sync.aligned.m8n8.x4.shared.b16 {%0,%1,%2,%3}, [%4];"
                 : "=r"(r0), "=r"(r1), "=r"(r2), "=r"(r3) : "r"(addr));
}
__device__ __forceinline__ void ldsm_x4_t(uint32_t& r0, uint32_t& r1, uint32_t& r2,
                                          uint32_t& r3, uint32_t addr) {
    asm volatile("ldmatrix.sync.aligned.m8n8.x4.trans.shared.b16 {%0,%1,%2,%3}, [%4];"
                 : "=r"(r0), "=r"(r1), "=r"(r2), "=r"(r3) : "r"(addr));
}
__device__ __forceinline__ void mma_f16(float* d, const uint32_t* a,
                                        const uint32_t* b) {
    asm volatile(
        "mma.sync.aligned.m16n8k16.row.col.f32.f16.f16.f32 "
        "{%0,%1,%2,%3}, {%4,%5,%6,%7}, {%8,%9}, {%0,%1,%2,%3};"
        : "+f"(d[0]), "+f"(d[1]), "+f"(d[2]), "+f"(d[3])
        : "r"(a[0]), "r"(a[1]), "r"(a[2]), "r"(a[3]), "r"(b[0]), "r"(b[1]));
}
__device__ __forceinline__ void cp_async16(uint32_t saddr, const void* gptr) {
    asm volatile("cp.async.cg.shared.global [%0], [%1], 16;"
                 :: "r"(saddr), "l"(gptr) : "memory");
}
__device__ __forceinline__ void cp_async_commit() {
    asm volatile("cp.async.commit_group;" ::: "memory");
}
__device__ __forceinline__ void cp_async_wait0() {
    asm volatile("cp.async.wait_group 0;" ::: "memory");
}
__device__ __forceinline__ void cp_async_wait1() {
    asm volatile("cp.async.wait_group 1;" ::: "memory");
}
__device__ __forceinline__ unsigned pack2h(float a, float b) {
    __half2 t = __floats2half2_rn(a, b);
    return *reinterpret_cast<unsigned*>(&t);
}

__device__ __forceinline__ int edge_idx(const void* ei, int which, int e) {
    if (g_is64) return (int)((const long long*)ei)[(size_t)which * EE + e];
    return ((const int*)ei)[(size_t)which * EE + e];
}

// ---------------------------------------------------------------- setup
// Fused: zero deg/cnt + PARALLEL dtype probe (block 0, 128 lanes + shared OR).
__global__ void detect_init_kernel(const int* __restrict__ ei32) {
    __shared__ int nz;
    int i = blockIdx.x * blockDim.x + threadIdx.x;
    if (blockIdx.x == 0 && threadIdx.x == 0) nz = 0;
    if (blockIdx.x == 0) __syncthreads();
    if (i < NN) { g_deg[i] = 0; g_cnt[i] = 0; }
    if (blockIdx.x == 0) {
        if (threadIdx.x < 128 && ei32[2 * threadIdx.x + 1] != 0) atomicOr(&nz, 1);
        __syncthreads();
        if (threadIdx.x == 0) g_is64 = nz ? 0 : 1;
    }
}
__global__ void count_deg_kernel(const void* __restrict__ ei) {
    int e = blockIdx.x * blockDim.x + threadIdx.x;
    if (e < EE) {
        int d = edge_idx(ei, 1, e);
        if ((unsigned)d < (unsigned)NN) atomicAdd(&g_deg[d], 1);
    }
}

// -------- multi-block exclusive scan of g_deg -> g_rowoff
__global__ void __launch_bounds__(256) scan_partial_kernel() {
    __shared__ int s[256];
    int t = threadIdx.x;
    int idx = blockIdx.x * 256 + t;
    s[t] = (idx < NN) ? g_deg[idx] : 0;
    __syncthreads();
#pragma unroll
    for (int off = 128; off > 0; off >>= 1) {
        if (t < off) s[t] += s[t + off];
        __syncthreads();
    }
    if (t == 0) g_part[blockIdx.x] = s[0];
}
__global__ void __launch_bounds__(256) scan_part_scan_kernel() {
    __shared__ int s[256];
    int t = threadIdx.x;
    int v = (t < SCAN_NB) ? g_part[t] : 0;
    s[t] = v;
    __syncthreads();
#pragma unroll
    for (int off = 1; off < 256; off <<= 1) {
        int u = (t >= off) ? s[t - off] : 0;
        __syncthreads();
        s[t] += u;
        __syncthreads();
    }
    if (t < SCAN_NB) g_part[t] = s[t] - v;  // exclusive
}
__global__ void __launch_bounds__(256) rowoff_kernel() {
    __shared__ int s[256];
    int t = threadIdx.x;
    int idx = blockIdx.x * 256 + t;
    int v = (idx < NN) ? g_deg[idx] : 0;
    s[t] = v;
    __syncthreads();
#pragma unroll
    for (int off = 1; off < 256; off <<= 1) {
        int u = (t >= off) ? s[t - off] : 0;
        __syncthreads();
        s[t] += u;
        __syncthreads();
    }
    if (idx <= NN) g_rowoff[idx] = g_part[blockIdx.x] + (s[t] - v);
}

__global__ void fill_csr_kernel(const void* __restrict__ ei) {
    int e = blockIdx.x * blockDim.x + threadIdx.x;
    if (e >= EE) return;
    int s = edge_idx(ei, 0, e);
    int d = edge_idx(ei, 1, e);
    if ((unsigned)s >= (unsigned)NN || (unsigned)d >= (unsigned)NN) return;
    int pos = g_rowoff[d] + atomicAdd(&g_cnt[d], 1);
    g_csr[pos] = s;
}

// ---------------------------------------------------------------- W converts
__global__ void __launch_bounds__(256) split_W1_kernel(const float* __restrict__ W1) {
    int i = blockIdx.x * blockDim.x + threadIdx.x;
    if (i >= F1 * F2) return;
    __half h = __float2half_rn(W1[i]);
    g_B1h[i] = *reinterpret_cast<uint16_t*>(&h);
}
__global__ void __launch_bounds__(256) split_W2_kernel(const float* __restrict__ W2) {
    int i = blockIdx.x * blockDim.x + threadIdx.x;
    if (i >= F2 * F3) return;
    __half h = __float2half_rn(W2[i]);
    g_B2h[i] = *reinterpret_cast<uint16_t*>(&h);
}

// ---------------------------------------------------------------- GEMM (fp16 mma.sync, single product)
// C[m, n0+n] = rsqrt(deg[m]+1) * sum_k fp16(A[m,k]) * fp16(B[k, n0+n])
// CTA tile 128 x 128, 256 threads, 2 CTAs/SM, BK=32, 3-stage cp.async for B.
// AHALF: A already fp16 in gmem (pure copy to smem).
// CHALF: C written as packed half2.
#define SA_STRIDE 80
#define GEMM_N 128
#define GEMM_SB (GEMM_N * 2 + 16)      // 272
#define GEMM_AH 0
#define GEMM_BH (128 * SA_STRIDE)      // 10240
#define GEMM_BUFB (GEMM_BH + 32 * GEMM_SB)   // 18944
#define GEMM_SMEM (3 * GEMM_BUFB)            // 56832

template <int K, int BW, bool AHALF, bool CHALF>
__device__ __forceinline__ void gemm_mma_dev(const void* __restrict__ Av,
                                             const uint16_t* __restrict__ Bh,
                                             void* __restrict__ Cv) {
    constexpr int T = K / 32;

    extern __shared__ char smem[];
    const uint32_t sb = smem_u32(smem);
    const int tid = threadIdx.x;
    const int lane = tid & 31;
    const int wid = tid >> 5;           // 0..7
    const int wm = wid >> 1;            // 0..3  (rows wm*32)
    const int wn = wid & 1;             // 0..1  (cols wn*64)
    const int m0 = blockIdx.y * 128;
    const int n0 = blockIdx.x * GEMM_N;

    float acc[2][8][4];
#pragma unroll
    for (int a = 0; a < 2; a++)
#pragma unroll
        for (int b = 0; b < 8; b++)
#pragma unroll
            for (int c = 0; c < 4; c++) acc[a][b][c] = 0.f;

    float4 pa[4];
    uint2 pah[4];
    const int ar = tid >> 3, ac = tid & 7;

    auto load_A = [&](int t) {
#pragma unroll
        for (int j = 0; j < 4; j++) {
            int row = ar + j * 32;
            bool ok = (m0 + row < NN);
            if (AHALF) {
                const uint16_t* xa = (const uint16_t*)Av + (size_t)m0 * K + t * 32;
                pah[j] = ok ? *reinterpret_cast<const uint2*>(xa + (size_t)row * K + ac * 4)
                            : make_uint2(0u, 0u);
            } else {
                const float* xa = (const float*)Av + (size_t)m0 * K + t * 32;
                pa[j] = ok ? *reinterpret_cast<const float4*>(xa + (size_t)row * K + ac * 4)
                           : make_float4(0.f, 0.f, 0.f, 0.f);
            }
        }
    };

    auto issue_B = [&](int t, int buf) {
        const uint16_t* bh = Bh + (size_t)(t * 32) * BW + n0;
        const uint32_t base = sb + buf * GEMM_BUFB;
#pragma unroll
        for (int i = 0; i < 2; i++) {
            int idx = tid + i * 256;
            int k = idx >> 4, c = idx & 15;
            cp_async16(base + GEMM_BH + k * GEMM_SB + c * 16, bh + (size_t)k * BW + c * 8);
        }
        cp_async_commit();
    };

    auto store_A = [&](int buf) {
        char* sbuf = smem + buf * GEMM_BUFB;
#pragma unroll
        for (int j = 0; j < 4; j++) {
            int r = ar + j * 32;
            uint2 hi;
            if (AHALF) {
                hi = pah[j];
            } else {
                float4 v = pa[j];
                hi = make_uint2(pack2h(v.x, v.y), pack2h(v.z, v.w));
            }
            *reinterpret_cast<uint2*>(sbuf + GEMM_AH + r * SA_STRIDE + ac * 8) = hi;
        }
    };

    auto compute = [&](int buf) {
        const uint32_t bufb = sb + buf * GEMM_BUFB;
#pragma unroll
        for (int ks = 0; ks < 2; ks++) {
            uint32_t Ah[2][4];
#pragma unroll
            for (int mi = 0; mi < 2; mi++) {
                uint32_t addr = bufb + GEMM_AH +
                                (wm * 32 + mi * 16 + (lane & 15)) * SA_STRIDE +
                                (ks * 16 + (lane >> 4) * 8) * 2;
                ldsm_x4(Ah[mi][0], Ah[mi][1], Ah[mi][2], Ah[mi][3], addr);
            }
#pragma unroll
            for (int np = 0; np < 4; np++) {
                uint32_t baddr = bufb + GEMM_BH + (ks * 16 + (lane & 15)) * GEMM_SB +
                                 (wn * 64 + np * 16 + (lane >> 4) * 8) * 2;
                uint32_t bh[4];
                ldsm_x4_t(bh[0], bh[1], bh[2], bh[3], baddr);
                mma_f16(acc[0][np * 2 + 0], Ah[0], bh + 0);
                mma_f16(acc[1][np * 2 + 0], Ah[1], bh + 0);
                mma_f16(acc[0][np * 2 + 1], Ah[0], bh + 2);
                mma_f16(acc[1][np * 2 + 1], Ah[1], bh + 2);
            }
        }
    };

    // prologue: stage 0 fully, B(1) in flight, A(1) in regs
    load_A(0);
    issue_B(0, 0);
    store_A(0);
    load_A(1);
    issue_B(1, 1);
    cp_async_wait1();
    __syncthreads();

    int b0 = 0, b1 = 1, b2 = 2;
    for (int t = 0; t < T; t++) {
        if (t + 1 < T) store_A(b1);
        if (t + 2 < T) { load_A(t + 2); issue_B(t + 2, b2); }
        compute(b0);
        if (t + 1 < T) {
            if (t + 2 < T) cp_async_wait1(); else cp_async_wait0();
            __syncthreads();
        }
        int tmp = b0; b0 = b1; b1 = b2; b2 = tmp;
    }

    // epilogue: scale by rsqrt(deg+1), write C
#pragma unroll
    for (int mi = 0; mi < 2; mi++) {
        int r0 = m0 + wm * 32 + mi * 16 + (lane >> 2);
        int r1 = r0 + 8;
        float s0 = (r0 < NN) ? rsqrtf((float)g_deg[r0] + 1.0f) : 0.f;
        float s1 = (r1 < NN) ? rsqrtf((float)g_deg[r1] + 1.0f) : 0.f;
#pragma unroll
        for (int nt = 0; nt < 8; nt++) {
            int col = n0 + wn * 64 + nt * 8 + (lane & 3) * 2;
            if (CHALF) {
                uint32_t* Ch = (uint32_t*)Cv;
                if (r0 < NN)
                    Ch[((size_t)r0 * BW + col) >> 1] =
                        pack2h(acc[mi][nt][0] * s0, acc[mi][nt][1] * s0);
                if (r1 < NN)
                    Ch[((size_t)r1 * BW + col) >> 1] =
                        pack2h(acc[mi][nt][2] * s1, acc[mi][nt][3] * s1);
            } else {
                float* Cf = (float*)Cv;
                if (r0 < NN) {
                    float2 v = make_float2(acc[mi][nt][0] * s0, acc[mi][nt][1] * s0);
                    *reinterpret_cast<float2*>(Cf + (size_t)r0 * BW + col) = v;
                }
                if (r1 < NN) {
                    float2 v = make_float2(acc[mi][nt][2] * s1, acc[mi][nt][3] * s1);
                    *reinterpret_cast<float2*>(Cf + (size_t)r1 * BW + col) = v;
                }
            }
        }
    }
}

__global__ void __launch_bounds__(256, 2) gemm1_kernel(const float* __restrict__ x) {
    gemm_mma_dev<F1, F2, false, true>(x, g_B1h, g_g1);
}
__global__ void __launch_bounds__(256, 2) gemm2_kernel() {
    gemm_mma_dev<F2, F3, true, true>(g_h1, g_B2h, g_g2);
}

// ---------------------------------------------------------------- aggregation
// Layer 1 (half2 in / half2 out):
// h1[d,:] = relu( rsqrt(deg+1) * (g1[d,:] + sum_{s} g1[s,:]) + b1 )
__global__ void __launch_bounds__(F2 / 2) agg1_kernel(const float* __restrict__ b1) {
    __shared__ int s_idx[F2 / 2];
    const __half2* g = reinterpret_cast<const __half2*>(g_g1);
    int d = blockIdx.x;
    int c = threadIdx.x;                 // half2 column 0..127
    int start = g_rowoff[d];
    int end = g_rowoff[d + 1];

    float2 acc = __half22float2(g[(size_t)d * (F2 / 2) + c]);   // self loop
    float2 acc2 = make_float2(0.f, 0.f);
    for (int base = start; base < end; base += F2 / 2) {
        int n = min(F2 / 2, end - base);
        __syncthreads();
        if (c < n) s_idx[c] = g_csr[base + c];
        __syncthreads();
        int i = 0;
        for (; i + 1 < n; i += 2) {
            float2 f0 = __half22float2(g[(size_t)s_idx[i] * (F2 / 2) + c]);
            float2 f1 = __half22float2(g[(size_t)s_idx[i + 1] * (F2 / 2) + c]);
            acc.x += f0.x; acc.y += f0.y;
            acc2.x += f1.x; acc2.y += f1.y;
        }
        if (i < n) {
            float2 f0 = __half22float2(g[(size_t)s_idx[i] * (F2 / 2) + c]);
            acc.x += f0.x; acc.y += f0.y;
        }
    }
    acc.x += acc2.x; acc.y += acc2.y;

    float s = rsqrtf((float)g_deg[d] + 1.0f);
    float2 bb = *reinterpret_cast<const float2*>(b1 + c * 2);
    float rx = fmaxf(fmaf(acc.x, s, bb.x), 0.f);
    float ry = fmaxf(fmaf(acc.y, s, bb.y), 0.f);
    reinterpret_cast<__half2*>(g_h1)[(size_t)d * (F2 / 2) + c] = __floats2half2_rn(rx, ry);
}

// Layer 2 (half2 in / fp32 out):
// out[d,:] = rsqrt(deg+1) * (g2[d,:] + sum_{s} g2[s,:]) + b2
__global__ void __launch_bounds__(F3 / 2) agg2_kernel(const float* __restrict__ b2,
                                                      float* __restrict__ out) {
    __shared__ int s_idx[F3 / 2];
    const __half2* g = reinterpret_cast<const __half2*>(g_g2);
    int d = blockIdx.x;
    int c = threadIdx.x;                 // half2 column 0..63
    int start = g_rowoff[d];
    int end = g_rowoff[d + 1];

    float2 acc = __half22float2(g[(size_t)d * (F3 / 2) + c]);   // self loop
    float2 acc2 = make_float2(0.f, 0.f);
    for (int base = start; base < end; base += F3 / 2) {
        int n = min(F3 / 2, end - base);
        __syncthreads();
        if (c < n) s_idx[c] = g_csr[base + c];
        __syncthreads();
        int i = 0;
        for (; i + 1 < n; i += 2) {
            float2 f0 = __half22float2(g[(size_t)s_idx[i] * (F3 / 2) + c]);
            float2 f1 = __half22float2(g[(size_t)s_idx[i + 1] * (F3 / 2) + c]);
            acc.x += f0.x; acc.y += f0.y;
            acc2.x += f1.x; acc2.y += f1.y;
        }
        if (i < n) {
            float2 f0 = __half22float2(g[(size_t)s_idx[i] * (F3 / 2) + c]);
            acc.x += f0.x; acc.y += f0.y;
        }
    }
    acc.x += acc2.x; acc.y += acc2.y;

    float s = rsqrtf((float)g_deg[d] + 1.0f);
    float2 bb = *reinterpret_cast<const float2*>(b2 + c * 2);
    float2 r;
    r.x = fmaf(acc.x, s, bb.x);
    r.y = fmaf(acc.y, s, bb.y);
    *reinterpret_cast<float2*>(out + (size_t)d * F3 + c * 2) = r;
}

// ---------------------------------------------------------------- launch
extern "C" void kernel_launch(void* const* d_in, const int* in_sizes, int n_in,
                              void* d_out, int out_size) {
    const float* x = (const float*)d_in[0];
    const void* ei = d_in[1];
    const float* W1 = (const float*)d_in[2];
    const float* b1 = (const float*)d_in[3];
    const float* W2 = (const float*)d_in[4];
    const float* b2 = (const float*)d_in[5];
    float* out = (float*)d_out;

    // One-time resources (created outside any graph capture side effects on
    // device memory; streams/events are host objects).
    static cudaStream_t s_side = nullptr;
    static cudaEvent_t ev_fork = nullptr, ev_join = nullptr;
    if (s_side == nullptr) {
        cudaStreamCreateWithFlags(&s_side, cudaStreamNonBlocking);
        cudaEventCreateWithFlags(&ev_fork, cudaEventDisableTiming);
        cudaEventCreateWithFlags(&ev_join, cudaEventDisableTiming);
        cudaFuncSetAttribute(gemm1_kernel,
                             cudaFuncAttributeMaxDynamicSharedMemorySize, GEMM_SMEM);
        cudaFuncSetAttribute(gemm2_kernel,
                             cudaFuncAttributeMaxDynamicSharedMemorySize, GEMM_SMEM);
    }

    // Stream 0 (capture stream): gemm1 is the 4th launch (ncu capture slot).
    split_W1_kernel<<<(F1 * F2 + 255) / 256, 256>>>(W1);            // 1
    detect_init_kernel<<<(NN + 255) / 256, 256>>>((const int*)ei);  // 2
    count_deg_kernel<<<(EE + 255) / 256, 256>>>(ei);                // 3

    // Fork: CSR build + W2 convert run concurrently with gemm1 (they depend
    // only on g_deg / ei / W2, none of which gemm1 writes).
    cudaEventRecord(ev_fork, 0);
    cudaStreamWaitEvent(s_side, ev_fork, 0);

    {
        dim3 grid(F2 / GEMM_N, (NN + 127) / 128);                   // (2, 391)
        gemm1_kernel<<<grid, 256, GEMM_SMEM>>>(x);                  // 4
    }

    scan_partial_kernel<<<SCAN_NB, 256, 0, s_side>>>();
    scan_part_scan_kernel<<<1, 256, 0, s_side>>>();
    rowoff_kernel<<<SCAN_NB, 256, 0, s_side>>>();
    fill_csr_kernel<<<(EE + 255) / 256, 256, 0, s_side>>>(ei);
    split_W2_kernel<<<(F2 * F3 + 255) / 256, 256, 0, s_side>>>(W2);

    // Join: agg1 needs gemm1 (stream 0) AND fill_csr (side stream).
    cudaEventRecord(ev_join, s_side);
    cudaStreamWaitEvent(0, ev_join, 0);

    agg1_kernel<<<NN, F2 / 2>>>(b1);
    {
        dim3 grid(F3 / GEMM_N, (NN + 127) / 128);                   // (1, 391)
        gemm2_kernel<<<grid, 256, GEMM_SMEM>>>();
    }
    agg2_kernel<<<NN, F3 / 2>>>(b2, out);
}